// round 14
// baseline (speedup 1.0000x reference)
#include <cuda_runtime.h>

#define NB 4
#define DK 256
#define DV 516
#define HW 4096
#define LM 32
#define DSP 2           // d sub-splits inside attn block (32 d each)
#define DQ 4            // d-splits across gridDim.y (64 d per block)

#define CCH 14          // out c-chunk: 37 chunks x 32 hw-tiles = 1184 = 4 waves x 296
#define NCH 37
#define OST 4           // out cp.async ring stages

// temp = log2(32*64*64 + 64*64) / sqrt(256)
#define TEMP 1.06527463f

// packed f32x2 FMA: d = a*b + d, lane-wise (2 independent IEEE fp32 fmas)
#define FMA_F32X2(d, a, b) \
    asm("fma.rn.f32x2 %0, %1, %2, %0;" : "+l"(d) : "l"(a), "l"(b))
// duplicate one fp32 into both lanes of a 64-bit packed register
#define PACK_DUP_F32X2(out, f) \
    asm("mov.b64 %0, {%1, %1};" : "=l"(out) : "r"(__float_as_uint(f)))

// cp.async: 16B global->shared, scoreboard-free (arbitrary pipeline depth)
#define CP_ASYNC16(dst_u32, src_ptr) \
    asm volatile("cp.async.cg.shared.global [%0], [%1], 16;" \
                 :: "r"(dst_u32), "l"(src_ptr))
#define CP_ASYNC_COMMIT() asm volatile("cp.async.commit_group;")
#define CP_ASYNC_WAIT(n)  asm volatile("cp.async.wait_group %0;" :: "n"(n))

// Scratch (static device allocations only; no cudaMalloc anywhere)
__device__ float g_q[NB * DK * HW];            // 16 MB: q[b][d][hw], pre-scaled
__device__ float g_attn[NB * LM * HW];         // 2 MB:  attn[b][m][hw]
__device__ float g_part[DQ * NB * LM * HW];    // 8 MB:  partial scores

// ---------------------------------------------------------------------------
// Kernel 1: q[b][d][hw] = TEMP * sum_c Q[c][d] * fc[b][c][hw]
// 128x128 block tile, BK=8, 256 threads, 8x8 register tile, double-buffered
// smem + register fragments, packed fma.rn.f32x2 inner product.
// ---------------------------------------------------------------------------
__global__ __launch_bounds__(256, 2) void qproj_kernel(
    const float* __restrict__ fc, const float* __restrict__ Qm) {
    __shared__ float As[2][8][128];   // [buf][c][d]
    __shared__ float Bs[2][8][128];   // [buf][c][hw]

    const int b   = blockIdx.z;
    const int d0  = blockIdx.y * 128;
    const int hw0 = blockIdx.x * 128;
    const int tid = threadIdx.x;
    const int tx  = tid & 15;        // hw tile coord (x8)
    const int ty  = tid >> 4;        // d  tile coord (x8)

    const float* fcb = fc + (size_t)b * DK * HW;

    const int lr = tid >> 5;          // 0..7  (c within tile)
    const int lc = (tid & 31) * 4;    // 0..124

    unsigned long long acc2[8][4];
#pragma unroll
    for (int i = 0; i < 8; i++)
#pragma unroll
        for (int j = 0; j < 4; j++) acc2[i][j] = 0ull;

    float4 pa = *(const float4*)(Qm + (size_t)lr * DK + d0 + lc);
    float4 pb = *(const float4*)(fcb + (size_t)lr * HW + hw0 + lc);
    *(float4*)&As[0][lr][lc] = pa;
    *(float4*)&Bs[0][lr][lc] = pb;
    __syncthreads();

    float fa[2][8];
    unsigned long long fb[2][4];

    int buf = 0;
    for (int k0 = 0; k0 < DK; k0 += 8) {
        const bool has_next = (k0 + 8) < DK;
        if (has_next) {
            pa = *(const float4*)(Qm + (size_t)(k0 + 8 + lr) * DK + d0 + lc);
            pb = *(const float4*)(fcb + (size_t)(k0 + 8 + lr) * HW + hw0 + lc);
        }

        *(float4*)(fa[0])     = *(const float4*)&As[buf][0][ty * 8];
        *(float4*)(fa[0] + 4) = *(const float4*)&As[buf][0][ty * 8 + 4];
        {
            ulonglong2 t0 = *(const ulonglong2*)&Bs[buf][0][tx * 8];
            ulonglong2 t1 = *(const ulonglong2*)&Bs[buf][0][tx * 8 + 4];
            fb[0][0] = t0.x; fb[0][1] = t0.y; fb[0][2] = t1.x; fb[0][3] = t1.y;
        }

#pragma unroll
        for (int k = 0; k < 8; k++) {
            const int cur = k & 1;
            const int nxt = cur ^ 1;
            if (k < 7) {
                *(float4*)(fa[nxt])     = *(const float4*)&As[buf][k + 1][ty * 8];
                *(float4*)(fa[nxt] + 4) = *(const float4*)&As[buf][k + 1][ty * 8 + 4];
                ulonglong2 t0 = *(const ulonglong2*)&Bs[buf][k + 1][tx * 8];
                ulonglong2 t1 = *(const ulonglong2*)&Bs[buf][k + 1][tx * 8 + 4];
                fb[nxt][0] = t0.x; fb[nxt][1] = t0.y;
                fb[nxt][2] = t1.x; fb[nxt][3] = t1.y;
            }
#pragma unroll
            for (int i = 0; i < 8; i++) {
                unsigned long long a2;
                PACK_DUP_F32X2(a2, fa[cur][i]);
                FMA_F32X2(acc2[i][0], a2, fb[cur][0]);
                FMA_F32X2(acc2[i][1], a2, fb[cur][1]);
                FMA_F32X2(acc2[i][2], a2, fb[cur][2]);
                FMA_F32X2(acc2[i][3], a2, fb[cur][3]);
            }
        }

        if (has_next) {
            *(float4*)&As[buf ^ 1][lr][lc] = pa;
            *(float4*)&Bs[buf ^ 1][lr][lc] = pb;
            __syncthreads();
            buf ^= 1;
        }
    }

    float* qo = g_q + (size_t)b * DK * HW;
#pragma unroll
    for (int i = 0; i < 8; i++) {
        float* dst = qo + (size_t)(d0 + ty * 8 + i) * HW + hw0 + tx * 8;
        const float* af = (const float*)acc2[i];
        float4 v0, v1;
        v0.x = af[0] * TEMP; v0.y = af[1] * TEMP;
        v0.z = af[2] * TEMP; v0.w = af[3] * TEMP;
        v1.x = af[4] * TEMP; v1.y = af[5] * TEMP;
        v1.z = af[6] * TEMP; v1.w = af[7] * TEMP;
        *(float4*)(dst)     = v0;
        *(float4*)(dst + 4) = v1;
    }
}

// ---------------------------------------------------------------------------
// Kernel 2a v3: partial scores with hw-PAIRS (LDG.64 + native f32x2 FMA).
// Block 256 = 32 lanes x 4 ms (8 m) x 2 ds (32 d). Grid (HW/64, DQ).
// ---------------------------------------------------------------------------
__global__ __launch_bounds__(256) void attn_partial_kernel(
    const float* __restrict__ key) {
    extern __shared__ float s_red[];   // [DSP][LM][NB][64] = 64KB

    const int tid  = threadIdx.x;
    const int lane = tid & 31;           // hw pair index
    const int ms   = (tid >> 5) & 3;     // m group (8 m)
    const int ds   = tid >> 7;           // d sub-split (32 d each)
    const int hw2  = blockIdx.x * 64 + lane * 2;
    const int dq   = blockIdx.y;
    const int dbase = dq * 64 + ds * 32;

    const float* qp[NB];
#pragma unroll
    for (int b = 0; b < NB; b++)
        qp[b] = g_q + (size_t)b * DK * HW + (size_t)dbase * HW + hw2;
    const float* kp[8];
#pragma unroll
    for (int j = 0; j < 8; j++)
        kp[j] = key + (size_t)(ms * 8 + j) * DK * HW + (size_t)dbase * HW + hw2;

    unsigned long long acc2[NB][8];
#pragma unroll
    for (int b = 0; b < NB; b++)
#pragma unroll
        for (int j = 0; j < 8; j++) acc2[b][j] = 0ull;

    for (int d = 0; d < 32; d += 4) {
#pragma unroll
        for (int u = 0; u < 4; u++) {
            unsigned long long q2[NB];
#pragma unroll
            for (int b = 0; b < NB; b++)
                q2[b] = *(const unsigned long long*)(qp[b] + u * HW);
#pragma unroll
            for (int j = 0; j < 8; j++) {
                const unsigned long long k2 =
                    *(const unsigned long long*)(kp[j] + u * HW);
                FMA_F32X2(acc2[0][j], q2[0], k2);
                FMA_F32X2(acc2[1][j], q2[1], k2);
                FMA_F32X2(acc2[2][j], q2[2], k2);
                FMA_F32X2(acc2[3][j], q2[3], k2);
            }
        }
#pragma unroll
        for (int b = 0; b < NB; b++) qp[b] += 4 * HW;
#pragma unroll
        for (int j = 0; j < 8; j++) kp[j] += 4 * HW;
    }

    // stash partials: s_red[ds][m][b][2*lane .. 2*lane+1]
#pragma unroll
    for (int b = 0; b < NB; b++)
#pragma unroll
        for (int j = 0; j < 8; j++)
            *(unsigned long long*)
                &s_red[(((ds * LM) + ms * 8 + j) * NB + b) * 64 + 2 * lane] =
                    acc2[b][j];
    __syncthreads();

    // reduce ds and write: 256 threads = 64 hw x 4 b
    {
        const int l   = tid & 63;
        const int b   = tid >> 6;
        const int hwg = blockIdx.x * 64 + l;
        float* pp = g_part + (((size_t)dq * NB + b) * LM) * HW + hwg;
#pragma unroll
        for (int m = 0; m < LM; m++) {
            const float v = s_red[((0 * LM + m) * NB + b) * 64 + l]
                          + s_red[((1 * LM + m) * NB + b) * 64 + l];
            pp[(size_t)m * HW] = v;
        }
    }
}

// ---------------------------------------------------------------------------
// Kernel 2b v2: finish — dq-parallel partial loads, smem reduce, softmax.
// Block 512 = 32 hw x 4 b x 4 dq-threads. Grid 128. smem 64KB.
// ---------------------------------------------------------------------------
__global__ __launch_bounds__(512) void attn_finish_kernel() {
    extern __shared__ float sf[];    // [DQ][NB][LM][32] = 64KB

    const int tid = threadIdx.x;
    const int l   = tid & 31;
    const int b   = (tid >> 5) & 3;
    const int dqt = tid >> 7;
    const int hw  = blockIdx.x * 32 + l;

    {
        const float* pp = g_part + (((size_t)dqt * NB + b) * LM) * HW + hw;
        float* dst = &sf[((dqt * NB + b) * LM) * 32 + l];
#pragma unroll
        for (int m = 0; m < LM; m++)
            dst[m * 32] = pp[(size_t)m * HW];
    }
    __syncthreads();

    if (tid < 128) {
        const int bb  = tid >> 5;
        const int ll  = tid & 31;
        const int hwg = blockIdx.x * 32 + ll;
        float s[LM];
        float mx = -1e30f;
#pragma unroll
        for (int m = 0; m < LM; m++) {
            const float v = sf[((0 * NB + bb) * LM + m) * 32 + ll]
                          + sf[((1 * NB + bb) * LM + m) * 32 + ll]
                          + sf[((2 * NB + bb) * LM + m) * 32 + ll]
                          + sf[((3 * NB + bb) * LM + m) * 32 + ll];
            s[m] = v;
            mx = fmaxf(mx, v);
        }
        float sum = 0.0f;
#pragma unroll
        for (int m = 0; m < LM; m++) { s[m] = __expf(s[m] - mx); sum += s[m]; }
        const float inv = 1.0f / sum;
        float* ap = g_attn + (size_t)bb * LM * HW + hwg;
#pragma unroll
        for (int m = 0; m < LM; m++) ap[(size_t)m * HW] = s[m] * inv;
    }
}

// ---------------------------------------------------------------------------
// Kernel 3 v6: out via 4-stage cp.async ring (64KB dynamic smem).
// R13's 2-stage ring kept only 1 stage (16KB) in DRAM flight -> 59% DRAM.
// 4 stages with wait_group 3 keep THREE stages (48KB/block, 96KB/SM) in
// flight. Compute loop, accumulator chains, grid (1184 = 4.0 waves @ 2
// blocks/SM) identical to R13 -> reduction order bit-identical.
// Stage reuse is 4 iterations apart, fenced by the trailing __syncthreads.
// ---------------------------------------------------------------------------
__global__ __launch_bounds__(256, 2) void out_kernel(
    const float* __restrict__ fm, const float* __restrict__ val,
    float* __restrict__ out) {
    extern __shared__ float vs[];       // [OST][LM][128] = 64KB ring

    const int tid = threadIdx.x;
    const int hwl = tid & 127;
    const int bg  = tid >> 7;
    const int hw0 = blockIdx.x * 128;
    const int hw  = hw0 + hwl;
    const int c0  = blockIdx.y * CCH;
    const int nc  = (c0 + CCH < DV) ? CCH : (DV - c0);
    const int b0  = bg * 2;
    const int b1  = b0 + 1;

    float a0[LM], a1[LM];
    {
        const float* ap0 = g_attn + (size_t)b0 * LM * HW + hw;
        const float* ap1 = g_attn + (size_t)b1 * LM * HW + hw;
#pragma unroll
        for (int m = 0; m < LM; m++) {
            a0[m] = ap0[(size_t)m * HW];
            a1[m] = ap1[(size_t)m * HW];
        }
    }

    const unsigned vs_base = (unsigned)__cvta_generic_to_shared(vs);
    const float* vsrc0 = val + hw0;

    // stage issuer: 1024 float4 units per stage, 4 per thread, coalesced
#define OUT_ISSUE_STAGE(stage, c)                                          \
    do {                                                                   \
        const float* _sb = vsrc0 + (size_t)(c) * HW;                       \
        _Pragma("unroll")                                                  \
        for (int _s = 0; _s < 4; _s++) {                                   \
            const int _idx = _s * 256 + tid;                               \
            const int _m   = _idx >> 5;                                    \
            const int _l4  = _idx & 31;                                    \
            const float* _src = _sb + (size_t)_m * DV * HW + _l4 * 4;      \
            const unsigned _dst = vs_base +                                \
                (((stage) * LM + _m) * 128 + _l4 * 4) * 4u;                \
            CP_ASYNC16(_dst, _src);                                        \
        }                                                                  \
        CP_ASYNC_COMMIT();                                                 \
    } while (0)

    // prologue: 3 stages in flight (nc >= 12 always)
    OUT_ISSUE_STAGE(0, c0);
    OUT_ISSUE_STAGE(1, c0 + 1);
    OUT_ISSUE_STAGE(2, c0 + 2);

    const float* fmp0 = fm + (size_t)b0 * DV * HW + hw;
    const float* fmp1 = fm + (size_t)b1 * DV * HW + hw;
    float*       op0  = out + (size_t)b0 * DV * HW + hw;
    float*       op1  = out + (size_t)b1 * DV * HW + hw;

    for (int cc = 0; cc < nc; cc++) {
        if (cc + 3 < nc) {
            OUT_ISSUE_STAGE((cc + 3) & (OST - 1), c0 + cc + 3);
            CP_ASYNC_WAIT(3);
        } else {
            const int rem = nc - 1 - cc;          // 2, 1, 0
            if (rem == 2)      CP_ASYNC_WAIT(2);
            else if (rem == 1) CP_ASYNC_WAIT(1);
            else               CP_ASYNC_WAIT(0);
        }
        __syncthreads();

        const int c = c0 + cc;
        const float* vrow = vs + (size_t)(cc & (OST - 1)) * LM * 128 + hwl;
        float s0 = 0.0f, s1 = 0.0f, t0 = 0.0f, t1 = 0.0f;
#pragma unroll
        for (int m = 0; m < LM; m += 2) {
            const float v0 = vrow[(size_t)m * 128];
            const float v1 = vrow[(size_t)(m + 1) * 128];
            s0 += a0[m] * v0;     t0 += a1[m] * v0;
            s1 += a0[m + 1] * v1; t1 += a1[m + 1] * v1;
        }
        op0[(size_t)c * HW] = fmp0[(size_t)c * HW] + 0.5f * (s0 + s1);
        op1[(size_t)c * HW] = fmp1[(size_t)c * HW] + 0.5f * (t0 + t1);

        __syncthreads();   // all reads of this stage done before its reuse
    }
#undef OUT_ISSUE_STAGE
}

// ---------------------------------------------------------------------------
// Launch. Inputs (metadata order): fc, fm, key_buffer, value_buffer, Q, K, V.
// concat(new, buffer)[-32:] keeps exactly the buffers -> K and V matrices are
// dead inputs; only q = fc@Q survives.
// ---------------------------------------------------------------------------
extern "C" void kernel_launch(void* const* d_in, const int* in_sizes, int n_in,
                              void* d_out, int out_size) {
    const float* fc   = (const float*)d_in[0];
    const float* fm   = (const float*)d_in[1];
    const float* keyb = (const float*)d_in[2];
    const float* valb = (const float*)d_in[3];
    const float* Qm   = (const float*)d_in[4];
    float* out = (float*)d_out;

    const int red_bytes = DSP * LM * NB * 64 * sizeof(float);  // 64KB
    const int fin_bytes = DQ * NB * LM * 32 * sizeof(float);   // 64KB
    const int out_bytes = OST * LM * 128 * sizeof(float);      // 64KB
    cudaFuncSetAttribute(attn_partial_kernel,
                         cudaFuncAttributeMaxDynamicSharedMemorySize, red_bytes);
    cudaFuncSetAttribute(attn_finish_kernel,
                         cudaFuncAttributeMaxDynamicSharedMemorySize, fin_bytes);
    cudaFuncSetAttribute(out_kernel,
                         cudaFuncAttributeMaxDynamicSharedMemorySize, out_bytes);

    qproj_kernel<<<dim3(HW / 128, DK / 128, NB), 256>>>(fc, Qm);
    attn_partial_kernel<<<dim3(HW / 64, DQ), 256, red_bytes>>>(keyb);
    attn_finish_kernel<<<dim3(HW / 32), 512, fin_bytes>>>();
    out_kernel<<<dim3(HW / 128, NCH), 256, out_bytes>>>(fm, valb, out);
}

// round 15
// speedup vs baseline: 1.0154x; 1.0154x over previous
#include <cuda_runtime.h>

#define NB 4
#define DK 256
#define DV 516
#define HW 4096
#define LM 32
#define DSP 2           // d sub-splits inside attn block (32 d each)
#define DQ 4            // d-splits across gridDim.y (64 d per block)

#define CCH 14          // out c-chunk: 37 chunks x 32 hw-tiles = 1184 = 4 waves x 296
#define NCH 37
#define OST 6           // out cp.async ring stages (reuse distance 3 > skew bound 2)

// temp = log2(32*64*64 + 64*64) / sqrt(256)
#define TEMP 1.06527463f

// packed f32x2 FMA: d = a*b + d, lane-wise (2 independent IEEE fp32 fmas)
#define FMA_F32X2(d, a, b) \
    asm("fma.rn.f32x2 %0, %1, %2, %0;" : "+l"(d) : "l"(a), "l"(b))
// duplicate one fp32 into both lanes of a 64-bit packed register
#define PACK_DUP_F32X2(out, f) \
    asm("mov.b64 %0, {%1, %1};" : "=l"(out) : "r"(__float_as_uint(f)))

// cp.async: 16B global->shared, scoreboard-free (arbitrary pipeline depth)
#define CP_ASYNC16(dst_u32, src_ptr) \
    asm volatile("cp.async.cg.shared.global [%0], [%1], 16;" \
                 :: "r"(dst_u32), "l"(src_ptr))
#define CP_ASYNC_COMMIT() asm volatile("cp.async.commit_group;")
#define CP_ASYNC_WAIT(n)  asm volatile("cp.async.wait_group %0;" :: "n"(n))

// Scratch (static device allocations only; no cudaMalloc anywhere)
__device__ float g_q[NB * DK * HW];            // 16 MB: q[b][d][hw], pre-scaled
__device__ float g_attn[NB * LM * HW];         // 2 MB:  attn[b][m][hw]
__device__ float g_part[DQ * NB * LM * HW];    // 8 MB:  partial scores

// ---------------------------------------------------------------------------
// Kernel 1: q[b][d][hw] = TEMP * sum_c Q[c][d] * fc[b][c][hw]
// 128x128 block tile, BK=8, 256 threads, 8x8 register tile, double-buffered
// smem + register fragments, packed fma.rn.f32x2 inner product.
// ---------------------------------------------------------------------------
__global__ __launch_bounds__(256, 2) void qproj_kernel(
    const float* __restrict__ fc, const float* __restrict__ Qm) {
    __shared__ float As[2][8][128];   // [buf][c][d]
    __shared__ float Bs[2][8][128];   // [buf][c][hw]

    const int b   = blockIdx.z;
    const int d0  = blockIdx.y * 128;
    const int hw0 = blockIdx.x * 128;
    const int tid = threadIdx.x;
    const int tx  = tid & 15;        // hw tile coord (x8)
    const int ty  = tid >> 4;        // d  tile coord (x8)

    const float* fcb = fc + (size_t)b * DK * HW;

    const int lr = tid >> 5;          // 0..7  (c within tile)
    const int lc = (tid & 31) * 4;    // 0..124

    unsigned long long acc2[8][4];
#pragma unroll
    for (int i = 0; i < 8; i++)
#pragma unroll
        for (int j = 0; j < 4; j++) acc2[i][j] = 0ull;

    float4 pa = *(const float4*)(Qm + (size_t)lr * DK + d0 + lc);
    float4 pb = *(const float4*)(fcb + (size_t)lr * HW + hw0 + lc);
    *(float4*)&As[0][lr][lc] = pa;
    *(float4*)&Bs[0][lr][lc] = pb;
    __syncthreads();

    float fa[2][8];
    unsigned long long fb[2][4];

    int buf = 0;
    for (int k0 = 0; k0 < DK; k0 += 8) {
        const bool has_next = (k0 + 8) < DK;
        if (has_next) {
            pa = *(const float4*)(Qm + (size_t)(k0 + 8 + lr) * DK + d0 + lc);
            pb = *(const float4*)(fcb + (size_t)(k0 + 8 + lr) * HW + hw0 + lc);
        }

        *(float4*)(fa[0])     = *(const float4*)&As[buf][0][ty * 8];
        *(float4*)(fa[0] + 4) = *(const float4*)&As[buf][0][ty * 8 + 4];
        {
            ulonglong2 t0 = *(const ulonglong2*)&Bs[buf][0][tx * 8];
            ulonglong2 t1 = *(const ulonglong2*)&Bs[buf][0][tx * 8 + 4];
            fb[0][0] = t0.x; fb[0][1] = t0.y; fb[0][2] = t1.x; fb[0][3] = t1.y;
        }

#pragma unroll
        for (int k = 0; k < 8; k++) {
            const int cur = k & 1;
            const int nxt = cur ^ 1;
            if (k < 7) {
                *(float4*)(fa[nxt])     = *(const float4*)&As[buf][k + 1][ty * 8];
                *(float4*)(fa[nxt] + 4) = *(const float4*)&As[buf][k + 1][ty * 8 + 4];
                ulonglong2 t0 = *(const ulonglong2*)&Bs[buf][k + 1][tx * 8];
                ulonglong2 t1 = *(const ulonglong2*)&Bs[buf][k + 1][tx * 8 + 4];
                fb[nxt][0] = t0.x; fb[nxt][1] = t0.y;
                fb[nxt][2] = t1.x; fb[nxt][3] = t1.y;
            }
#pragma unroll
            for (int i = 0; i < 8; i++) {
                unsigned long long a2;
                PACK_DUP_F32X2(a2, fa[cur][i]);
                FMA_F32X2(acc2[i][0], a2, fb[cur][0]);
                FMA_F32X2(acc2[i][1], a2, fb[cur][1]);
                FMA_F32X2(acc2[i][2], a2, fb[cur][2]);
                FMA_F32X2(acc2[i][3], a2, fb[cur][3]);
            }
        }

        if (has_next) {
            *(float4*)&As[buf ^ 1][lr][lc] = pa;
            *(float4*)&Bs[buf ^ 1][lr][lc] = pb;
            __syncthreads();
            buf ^= 1;
        }
    }

    float* qo = g_q + (size_t)b * DK * HW;
#pragma unroll
    for (int i = 0; i < 8; i++) {
        float* dst = qo + (size_t)(d0 + ty * 8 + i) * HW + hw0 + tx * 8;
        const float* af = (const float*)acc2[i];
        float4 v0, v1;
        v0.x = af[0] * TEMP; v0.y = af[1] * TEMP;
        v0.z = af[2] * TEMP; v0.w = af[3] * TEMP;
        v1.x = af[4] * TEMP; v1.y = af[5] * TEMP;
        v1.z = af[6] * TEMP; v1.w = af[7] * TEMP;
        *(float4*)(dst)     = v0;
        *(float4*)(dst + 4) = v1;
    }
}

// ---------------------------------------------------------------------------
// Kernel 2a v3: partial scores with hw-PAIRS (LDG.64 + native f32x2 FMA).
// Block 256 = 32 lanes x 4 ms (8 m) x 2 ds (32 d). Grid (HW/64, DQ).
// ---------------------------------------------------------------------------
__global__ __launch_bounds__(256) void attn_partial_kernel(
    const float* __restrict__ key) {
    extern __shared__ float s_red[];   // [DSP][LM][NB][64] = 64KB

    const int tid  = threadIdx.x;
    const int lane = tid & 31;           // hw pair index
    const int ms   = (tid >> 5) & 3;     // m group (8 m)
    const int ds   = tid >> 7;           // d sub-split (32 d each)
    const int hw2  = blockIdx.x * 64 + lane * 2;
    const int dq   = blockIdx.y;
    const int dbase = dq * 64 + ds * 32;

    const float* qp[NB];
#pragma unroll
    for (int b = 0; b < NB; b++)
        qp[b] = g_q + (size_t)b * DK * HW + (size_t)dbase * HW + hw2;
    const float* kp[8];
#pragma unroll
    for (int j = 0; j < 8; j++)
        kp[j] = key + (size_t)(ms * 8 + j) * DK * HW + (size_t)dbase * HW + hw2;

    unsigned long long acc2[NB][8];
#pragma unroll
    for (int b = 0; b < NB; b++)
#pragma unroll
        for (int j = 0; j < 8; j++) acc2[b][j] = 0ull;

    for (int d = 0; d < 32; d += 4) {
#pragma unroll
        for (int u = 0; u < 4; u++) {
            unsigned long long q2[NB];
#pragma unroll
            for (int b = 0; b < NB; b++)
                q2[b] = *(const unsigned long long*)(qp[b] + u * HW);
#pragma unroll
            for (int j = 0; j < 8; j++) {
                const unsigned long long k2 =
                    *(const unsigned long long*)(kp[j] + u * HW);
                FMA_F32X2(acc2[0][j], q2[0], k2);
                FMA_F32X2(acc2[1][j], q2[1], k2);
                FMA_F32X2(acc2[2][j], q2[2], k2);
                FMA_F32X2(acc2[3][j], q2[3], k2);
            }
        }
#pragma unroll
        for (int b = 0; b < NB; b++) qp[b] += 4 * HW;
#pragma unroll
        for (int j = 0; j < 8; j++) kp[j] += 4 * HW;
    }

    // stash partials: s_red[ds][m][b][2*lane .. 2*lane+1]
#pragma unroll
    for (int b = 0; b < NB; b++)
#pragma unroll
        for (int j = 0; j < 8; j++)
            *(unsigned long long*)
                &s_red[(((ds * LM) + ms * 8 + j) * NB + b) * 64 + 2 * lane] =
                    acc2[b][j];
    __syncthreads();

    // reduce ds and write: 256 threads = 64 hw x 4 b
    {
        const int l   = tid & 63;
        const int b   = tid >> 6;
        const int hwg = blockIdx.x * 64 + l;
        float* pp = g_part + (((size_t)dq * NB + b) * LM) * HW + hwg;
#pragma unroll
        for (int m = 0; m < LM; m++) {
            const float v = s_red[((0 * LM + m) * NB + b) * 64 + l]
                          + s_red[((1 * LM + m) * NB + b) * 64 + l];
            pp[(size_t)m * HW] = v;
        }
    }
}

// ---------------------------------------------------------------------------
// Kernel 2b v2: finish — dq-parallel partial loads, smem reduce, softmax.
// Block 512 = 32 hw x 4 b x 4 dq-threads. Grid 128. smem 64KB.
// ---------------------------------------------------------------------------
__global__ __launch_bounds__(512) void attn_finish_kernel() {
    extern __shared__ float sf[];    // [DQ][NB][LM][32] = 64KB

    const int tid = threadIdx.x;
    const int l   = tid & 31;
    const int b   = (tid >> 5) & 3;
    const int dqt = tid >> 7;
    const int hw  = blockIdx.x * 32 + l;

    {
        const float* pp = g_part + (((size_t)dqt * NB + b) * LM) * HW + hw;
        float* dst = &sf[((dqt * NB + b) * LM) * 32 + l];
#pragma unroll
        for (int m = 0; m < LM; m++)
            dst[m * 32] = pp[(size_t)m * HW];
    }
    __syncthreads();

    if (tid < 128) {
        const int bb  = tid >> 5;
        const int ll  = tid & 31;
        const int hwg = blockIdx.x * 32 + ll;
        float s[LM];
        float mx = -1e30f;
#pragma unroll
        for (int m = 0; m < LM; m++) {
            const float v = sf[((0 * NB + bb) * LM + m) * 32 + ll]
                          + sf[((1 * NB + bb) * LM + m) * 32 + ll]
                          + sf[((2 * NB + bb) * LM + m) * 32 + ll]
                          + sf[((3 * NB + bb) * LM + m) * 32 + ll];
            s[m] = v;
            mx = fmaxf(mx, v);
        }
        float sum = 0.0f;
#pragma unroll
        for (int m = 0; m < LM; m++) { s[m] = __expf(s[m] - mx); sum += s[m]; }
        const float inv = 1.0f / sum;
        float* ap = g_attn + (size_t)bb * LM * HW + hwg;
#pragma unroll
        for (int m = 0; m < LM; m++) ap[(size_t)m * HW] = s[m] * inv;
    }
}

// ---------------------------------------------------------------------------
// Kernel 3 v7: out via 6-stage cp.async ring, ONE barrier per c-iteration.
// R14 showed flight depth isn't the limiter; the remaining suspect is the
// 2-barriers-per-iter convoy. Skew bound: with one barrier per iter, when any
// warp is at iter cc, every warp has finished compute(cc-2) (it arrived at
// BAR(cc-1), which follows compute(cc-2) in program order). A 6-stage ring
// overwrites the buffer last read at iter cc-3 < cc-2 -> trailing barrier
// provably unnecessary. Flight depth still 3 (wait_group 3); the single
// barrier (after wait) makes all warps' stage-cc writes visible.
// Compute loop & reduction order bit-identical to R13/R14.
// 96KB dynamic smem, 2 blocks/SM (192KB of 228KB). Grid 1184 = 4.0 waves.
// ---------------------------------------------------------------------------
__global__ __launch_bounds__(256, 2) void out_kernel(
    const float* __restrict__ fm, const float* __restrict__ val,
    float* __restrict__ out) {
    extern __shared__ float vs[];       // [OST][LM][128] = 96KB ring

    const int tid = threadIdx.x;
    const int hwl = tid & 127;
    const int bg  = tid >> 7;
    const int hw0 = blockIdx.x * 128;
    const int hw  = hw0 + hwl;
    const int c0  = blockIdx.y * CCH;
    const int nc  = (c0 + CCH < DV) ? CCH : (DV - c0);
    const int b0  = bg * 2;
    const int b1  = b0 + 1;

    float a0[LM], a1[LM];
    {
        const float* ap0 = g_attn + (size_t)b0 * LM * HW + hw;
        const float* ap1 = g_attn + (size_t)b1 * LM * HW + hw;
#pragma unroll
        for (int m = 0; m < LM; m++) {
            a0[m] = ap0[(size_t)m * HW];
            a1[m] = ap1[(size_t)m * HW];
        }
    }

    const unsigned vs_base = (unsigned)__cvta_generic_to_shared(vs);
    const float* vsrc0 = val + hw0;

    // stage issuer: 1024 float4 units per stage, 4 per thread, coalesced
#define OUT_ISSUE_STAGE(stage, c)                                          \
    do {                                                                   \
        const float* _sb = vsrc0 + (size_t)(c) * HW;                       \
        _Pragma("unroll")                                                  \
        for (int _s = 0; _s < 4; _s++) {                                   \
            const int _idx = _s * 256 + tid;                               \
            const int _m   = _idx >> 5;                                    \
            const int _l4  = _idx & 31;                                    \
            const float* _src = _sb + (size_t)_m * DV * HW + _l4 * 4;      \
            const unsigned _dst = vs_base +                                \
                (((stage) * LM + _m) * 128 + _l4 * 4) * 4u;                \
            CP_ASYNC16(_dst, _src);                                        \
        }                                                                  \
        CP_ASYNC_COMMIT();                                                 \
    } while (0)

    // prologue: 3 stages in flight (nc >= 12 always)
    OUT_ISSUE_STAGE(0, c0);
    OUT_ISSUE_STAGE(1, c0 + 1);
    OUT_ISSUE_STAGE(2, c0 + 2);

    const float* fmp0 = fm + (size_t)b0 * DV * HW + hw;
    const float* fmp1 = fm + (size_t)b1 * DV * HW + hw;
    float*       op0  = out + (size_t)b0 * DV * HW + hw;
    float*       op1  = out + (size_t)b1 * DV * HW + hw;

    int stage = 0;                       // = cc % OST
    for (int cc = 0; cc < nc; cc++) {
        if (cc + 3 < nc) {
            int istage = stage + 3; if (istage >= OST) istage -= OST;
            OUT_ISSUE_STAGE(istage, c0 + cc + 3);
            CP_ASYNC_WAIT(3);
        } else {
            const int rem = nc - 1 - cc;          // 2, 1, 0
            if (rem == 2)      CP_ASYNC_WAIT(2);
            else if (rem == 1) CP_ASYNC_WAIT(1);
            else               CP_ASYNC_WAIT(0);
        }
        __syncthreads();   // stage-cc writes visible; bounds warp skew to 1 iter

        const int c = c0 + cc;
        const float* vrow = vs + (size_t)stage * LM * 128 + hwl;
        float s0 = 0.0f, s1 = 0.0f, t0 = 0.0f, t1 = 0.0f;
#pragma unroll
        for (int m = 0; m < LM; m += 2) {
            const float v0 = vrow[(size_t)m * 128];
            const float v1 = vrow[(size_t)(m + 1) * 128];
            s0 += a0[m] * v0;     t0 += a1[m] * v0;
            s1 += a0[m + 1] * v1; t1 += a1[m + 1] * v1;
        }
        op0[(size_t)c * HW] = fmp0[(size_t)c * HW] + 0.5f * (s0 + s1);
        op1[(size_t)c * HW] = fmp1[(size_t)c * HW] + 0.5f * (t0 + t1);

        if (++stage == OST) stage = 0;
    }
#undef OUT_ISSUE_STAGE
}

// ---------------------------------------------------------------------------
// Launch. Inputs (metadata order): fc, fm, key_buffer, value_buffer, Q, K, V.
// concat(new, buffer)[-32:] keeps exactly the buffers -> K and V matrices are
// dead inputs; only q = fc@Q survives.
// ---------------------------------------------------------------------------
extern "C" void kernel_launch(void* const* d_in, const int* in_sizes, int n_in,
                              void* d_out, int out_size) {
    const float* fc   = (const float*)d_in[0];
    const float* fm   = (const float*)d_in[1];
    const float* keyb = (const float*)d_in[2];
    const float* valb = (const float*)d_in[3];
    const float* Qm   = (const float*)d_in[4];
    float* out = (float*)d_out;

    const int red_bytes = DSP * LM * NB * 64 * sizeof(float);  // 64KB
    const int fin_bytes = DQ * NB * LM * 32 * sizeof(float);   // 64KB
    const int out_bytes = OST * LM * 128 * sizeof(float);      // 96KB
    cudaFuncSetAttribute(attn_partial_kernel,
                         cudaFuncAttributeMaxDynamicSharedMemorySize, red_bytes);
    cudaFuncSetAttribute(attn_finish_kernel,
                         cudaFuncAttributeMaxDynamicSharedMemorySize, fin_bytes);
    cudaFuncSetAttribute(out_kernel,
                         cudaFuncAttributeMaxDynamicSharedMemorySize, out_bytes);

    qproj_kernel<<<dim3(HW / 128, DK / 128, NB), 256>>>(fc, Qm);
    attn_partial_kernel<<<dim3(HW / 64, DQ), 256, red_bytes>>>(keyb);
    attn_finish_kernel<<<dim3(HW / 32), 512, fin_bytes>>>();
    out_kernel<<<dim3(HW / 128, NCH), 256, out_bytes>>>(fm, valb, out);
}

// round 16
// speedup vs baseline: 1.0219x; 1.0064x over previous
#include <cuda_runtime.h>

#define NB 4
#define DK 256
#define DV 516
#define HW 4096
#define HWC 2048        // hw per pipeline chunk (2 chunks x 2 streams)
#define LM 32
#define DSP 2           // d sub-splits inside attn block (32 d each)
#define DQ 4            // d-splits across gridDim.y (64 d per block)

#define CCH 14          // out c-chunk: 37 chunks
#define NCH 37
#define OST 6           // out cp.async ring stages

// temp = log2(32*64*64 + 64*64) / sqrt(256)
#define TEMP 1.06527463f

// packed f32x2 FMA: d = a*b + d, lane-wise (2 independent IEEE fp32 fmas)
#define FMA_F32X2(d, a, b) \
    asm("fma.rn.f32x2 %0, %1, %2, %0;" : "+l"(d) : "l"(a), "l"(b))
// duplicate one fp32 into both lanes of a 64-bit packed register
#define PACK_DUP_F32X2(out, f) \
    asm("mov.b64 %0, {%1, %1};" : "=l"(out) : "r"(__float_as_uint(f)))

// cp.async: 16B global->shared, scoreboard-free
#define CP_ASYNC16(dst_u32, src_ptr) \
    asm volatile("cp.async.cg.shared.global [%0], [%1], 16;" \
                 :: "r"(dst_u32), "l"(src_ptr))
#define CP_ASYNC_COMMIT() asm volatile("cp.async.commit_group;")
#define CP_ASYNC_WAIT(n)  asm volatile("cp.async.wait_group %0;" :: "n"(n))

// Scratch (static device allocations only; no cudaMalloc anywhere)
__device__ float g_q[NB * DK * HW];            // 16 MB: q[b][d][hw], pre-scaled
__device__ float g_attn[NB * LM * HW];         // 2 MB:  attn[b][m][hw]
__device__ float g_part[DQ * NB * LM * HW];    // 8 MB:  partial scores

// ---------------------------------------------------------------------------
// Kernel 1: q[b][d][hw] = TEMP * sum_c Q[c][d] * fc[b][c][hw]
// 128x128 block tile, BK=8, 256 threads, 8x8 register tile, double-buffered
// smem + register fragments, packed fma.rn.f32x2 inner product.
// hwb = pipeline-chunk hw offset.
// ---------------------------------------------------------------------------
__global__ __launch_bounds__(256, 2) void qproj_kernel(
    const float* __restrict__ fc, const float* __restrict__ Qm, int hwb) {
    __shared__ float As[2][8][128];   // [buf][c][d]
    __shared__ float Bs[2][8][128];   // [buf][c][hw]

    const int b   = blockIdx.z;
    const int d0  = blockIdx.y * 128;
    const int hw0 = hwb + blockIdx.x * 128;
    const int tid = threadIdx.x;
    const int tx  = tid & 15;        // hw tile coord (x8)
    const int ty  = tid >> 4;        // d  tile coord (x8)

    const float* fcb = fc + (size_t)b * DK * HW;

    const int lr = tid >> 5;          // 0..7  (c within tile)
    const int lc = (tid & 31) * 4;    // 0..124

    unsigned long long acc2[8][4];
#pragma unroll
    for (int i = 0; i < 8; i++)
#pragma unroll
        for (int j = 0; j < 4; j++) acc2[i][j] = 0ull;

    float4 pa = *(const float4*)(Qm + (size_t)lr * DK + d0 + lc);
    float4 pb = *(const float4*)(fcb + (size_t)lr * HW + hw0 + lc);
    *(float4*)&As[0][lr][lc] = pa;
    *(float4*)&Bs[0][lr][lc] = pb;
    __syncthreads();

    float fa[2][8];
    unsigned long long fb[2][4];

    int buf = 0;
    for (int k0 = 0; k0 < DK; k0 += 8) {
        const bool has_next = (k0 + 8) < DK;
        if (has_next) {
            pa = *(const float4*)(Qm + (size_t)(k0 + 8 + lr) * DK + d0 + lc);
            pb = *(const float4*)(fcb + (size_t)(k0 + 8 + lr) * HW + hw0 + lc);
        }

        *(float4*)(fa[0])     = *(const float4*)&As[buf][0][ty * 8];
        *(float4*)(fa[0] + 4) = *(const float4*)&As[buf][0][ty * 8 + 4];
        {
            ulonglong2 t0 = *(const ulonglong2*)&Bs[buf][0][tx * 8];
            ulonglong2 t1 = *(const ulonglong2*)&Bs[buf][0][tx * 8 + 4];
            fb[0][0] = t0.x; fb[0][1] = t0.y; fb[0][2] = t1.x; fb[0][3] = t1.y;
        }

#pragma unroll
        for (int k = 0; k < 8; k++) {
            const int cur = k & 1;
            const int nxt = cur ^ 1;
            if (k < 7) {
                *(float4*)(fa[nxt])     = *(const float4*)&As[buf][k + 1][ty * 8];
                *(float4*)(fa[nxt] + 4) = *(const float4*)&As[buf][k + 1][ty * 8 + 4];
                ulonglong2 t0 = *(const ulonglong2*)&Bs[buf][k + 1][tx * 8];
                ulonglong2 t1 = *(const ulonglong2*)&Bs[buf][k + 1][tx * 8 + 4];
                fb[nxt][0] = t0.x; fb[nxt][1] = t0.y;
                fb[nxt][2] = t1.x; fb[nxt][3] = t1.y;
            }
#pragma unroll
            for (int i = 0; i < 8; i++) {
                unsigned long long a2;
                PACK_DUP_F32X2(a2, fa[cur][i]);
                FMA_F32X2(acc2[i][0], a2, fb[cur][0]);
                FMA_F32X2(acc2[i][1], a2, fb[cur][1]);
                FMA_F32X2(acc2[i][2], a2, fb[cur][2]);
                FMA_F32X2(acc2[i][3], a2, fb[cur][3]);
            }
        }

        if (has_next) {
            *(float4*)&As[buf ^ 1][lr][lc] = pa;
            *(float4*)&Bs[buf ^ 1][lr][lc] = pb;
            __syncthreads();
            buf ^= 1;
        }
    }

    float* qo = g_q + (size_t)b * DK * HW;
#pragma unroll
    for (int i = 0; i < 8; i++) {
        float* dst = qo + (size_t)(d0 + ty * 8 + i) * HW + hw0 + tx * 8;
        const float* af = (const float*)acc2[i];
        float4 v0, v1;
        v0.x = af[0] * TEMP; v0.y = af[1] * TEMP;
        v0.z = af[2] * TEMP; v0.w = af[3] * TEMP;
        v1.x = af[4] * TEMP; v1.y = af[5] * TEMP;
        v1.z = af[6] * TEMP; v1.w = af[7] * TEMP;
        *(float4*)(dst)     = v0;
        *(float4*)(dst + 4) = v1;
    }
}

// ---------------------------------------------------------------------------
// Kernel 2a v3: partial scores with hw-PAIRS (LDG.64 + native f32x2 FMA).
// Block 256 = 32 lanes x 4 ms (8 m) x 2 ds (32 d). Grid (HWC/64, DQ).
// ---------------------------------------------------------------------------
__global__ __launch_bounds__(256) void attn_partial_kernel(
    const float* __restrict__ key, int hwb) {
    extern __shared__ float s_red[];   // [DSP][LM][NB][64] = 64KB

    const int tid  = threadIdx.x;
    const int lane = tid & 31;           // hw pair index
    const int ms   = (tid >> 5) & 3;     // m group (8 m)
    const int ds   = tid >> 7;           // d sub-split (32 d each)
    const int hw2  = hwb + blockIdx.x * 64 + lane * 2;
    const int dq   = blockIdx.y;
    const int dbase = dq * 64 + ds * 32;

    const float* qp[NB];
#pragma unroll
    for (int b = 0; b < NB; b++)
        qp[b] = g_q + (size_t)b * DK * HW + (size_t)dbase * HW + hw2;
    const float* kp[8];
#pragma unroll
    for (int j = 0; j < 8; j++)
        kp[j] = key + (size_t)(ms * 8 + j) * DK * HW + (size_t)dbase * HW + hw2;

    unsigned long long acc2[NB][8];
#pragma unroll
    for (int b = 0; b < NB; b++)
#pragma unroll
        for (int j = 0; j < 8; j++) acc2[b][j] = 0ull;

    for (int d = 0; d < 32; d += 4) {
#pragma unroll
        for (int u = 0; u < 4; u++) {
            unsigned long long q2[NB];
#pragma unroll
            for (int b = 0; b < NB; b++)
                q2[b] = *(const unsigned long long*)(qp[b] + u * HW);
#pragma unroll
            for (int j = 0; j < 8; j++) {
                const unsigned long long k2 =
                    *(const unsigned long long*)(kp[j] + u * HW);
                FMA_F32X2(acc2[0][j], q2[0], k2);
                FMA_F32X2(acc2[1][j], q2[1], k2);
                FMA_F32X2(acc2[2][j], q2[2], k2);
                FMA_F32X2(acc2[3][j], q2[3], k2);
            }
        }
#pragma unroll
        for (int b = 0; b < NB; b++) qp[b] += 4 * HW;
#pragma unroll
        for (int j = 0; j < 8; j++) kp[j] += 4 * HW;
    }

    // stash partials: s_red[ds][m][b][2*lane .. 2*lane+1]
#pragma unroll
    for (int b = 0; b < NB; b++)
#pragma unroll
        for (int j = 0; j < 8; j++)
            *(unsigned long long*)
                &s_red[(((ds * LM) + ms * 8 + j) * NB + b) * 64 + 2 * lane] =
                    acc2[b][j];
    __syncthreads();

    // reduce ds and write: 256 threads = 64 hw x 4 b
    {
        const int l   = tid & 63;
        const int b   = tid >> 6;
        const int hwg = hwb + blockIdx.x * 64 + l;
        float* pp = g_part + (((size_t)dq * NB + b) * LM) * HW + hwg;
#pragma unroll
        for (int m = 0; m < LM; m++) {
            const float v = s_red[((0 * LM + m) * NB + b) * 64 + l]
                          + s_red[((1 * LM + m) * NB + b) * 64 + l];
            pp[(size_t)m * HW] = v;
        }
    }
}

// ---------------------------------------------------------------------------
// Kernel 2b v2: finish — dq-parallel partial loads, smem reduce, softmax.
// Block 512 = 32 hw x 4 b x 4 dq-threads. Grid HWC/32. smem 64KB.
// ---------------------------------------------------------------------------
__global__ __launch_bounds__(512) void attn_finish_kernel(int hwb) {
    extern __shared__ float sf[];    // [DQ][NB][LM][32] = 64KB

    const int tid = threadIdx.x;
    const int l   = tid & 31;
    const int b   = (tid >> 5) & 3;
    const int dqt = tid >> 7;
    const int hw  = hwb + blockIdx.x * 32 + l;

    {
        const float* pp = g_part + (((size_t)dqt * NB + b) * LM) * HW + hw;
        float* dst = &sf[((dqt * NB + b) * LM) * 32 + l];
#pragma unroll
        for (int m = 0; m < LM; m++)
            dst[m * 32] = pp[(size_t)m * HW];
    }
    __syncthreads();

    if (tid < 128) {
        const int bb  = tid >> 5;
        const int ll  = tid & 31;
        const int hwg = hwb + blockIdx.x * 32 + ll;
        float s[LM];
        float mx = -1e30f;
#pragma unroll
        for (int m = 0; m < LM; m++) {
            const float v = sf[((0 * NB + bb) * LM + m) * 32 + ll]
                          + sf[((1 * NB + bb) * LM + m) * 32 + ll]
                          + sf[((2 * NB + bb) * LM + m) * 32 + ll]
                          + sf[((3 * NB + bb) * LM + m) * 32 + ll];
            s[m] = v;
            mx = fmaxf(mx, v);
        }
        float sum = 0.0f;
#pragma unroll
        for (int m = 0; m < LM; m++) { s[m] = __expf(s[m] - mx); sum += s[m]; }
        const float inv = 1.0f / sum;
        float* ap = g_attn + (size_t)bb * LM * HW + hwg;
#pragma unroll
        for (int m = 0; m < LM; m++) ap[(size_t)m * HW] = s[m] * inv;
    }
}

// ---------------------------------------------------------------------------
// Kernel 3 v7: out via 6-stage cp.async ring, one barrier per c-iteration.
// Grid (HWC/128, 37) = 592 blocks = exactly 2.0 waves at 2 blocks/SM.
// ---------------------------------------------------------------------------
__global__ __launch_bounds__(256, 2) void out_kernel(
    const float* __restrict__ fm, const float* __restrict__ val,
    float* __restrict__ out, int hwb) {
    extern __shared__ float vs[];       // [OST][LM][128] = 96KB ring

    const int tid = threadIdx.x;
    const int hwl = tid & 127;
    const int bg  = tid >> 7;
    const int hw0 = hwb + blockIdx.x * 128;
    const int hw  = hw0 + hwl;
    const int c0  = blockIdx.y * CCH;
    const int nc  = (c0 + CCH < DV) ? CCH : (DV - c0);
    const int b0  = bg * 2;
    const int b1  = b0 + 1;

    float a0[LM], a1[LM];
    {
        const float* ap0 = g_attn + (size_t)b0 * LM * HW + hw;
        const float* ap1 = g_attn + (size_t)b1 * LM * HW + hw;
#pragma unroll
        for (int m = 0; m < LM; m++) {
            a0[m] = ap0[(size_t)m * HW];
            a1[m] = ap1[(size_t)m * HW];
        }
    }

    const unsigned vs_base = (unsigned)__cvta_generic_to_shared(vs);
    const float* vsrc0 = val + hw0;

#define OUT_ISSUE_STAGE(stage, c)                                          \
    do {                                                                   \
        const float* _sb = vsrc0 + (size_t)(c) * HW;                       \
        _Pragma("unroll")                                                  \
        for (int _s = 0; _s < 4; _s++) {                                   \
            const int _idx = _s * 256 + tid;                               \
            const int _m   = _idx >> 5;                                    \
            const int _l4  = _idx & 31;                                    \
            const float* _src = _sb + (size_t)_m * DV * HW + _l4 * 4;      \
            const unsigned _dst = vs_base +                                \
                (((stage) * LM + _m) * 128 + _l4 * 4) * 4u;                \
            CP_ASYNC16(_dst, _src);                                        \
        }                                                                  \
        CP_ASYNC_COMMIT();                                                 \
    } while (0)

    OUT_ISSUE_STAGE(0, c0);
    OUT_ISSUE_STAGE(1, c0 + 1);
    OUT_ISSUE_STAGE(2, c0 + 2);

    const float* fmp0 = fm + (size_t)b0 * DV * HW + hw;
    const float* fmp1 = fm + (size_t)b1 * DV * HW + hw;
    float*       op0  = out + (size_t)b0 * DV * HW + hw;
    float*       op1  = out + (size_t)b1 * DV * HW + hw;

    int stage = 0;                       // = cc % OST
    for (int cc = 0; cc < nc; cc++) {
        if (cc + 3 < nc) {
            int istage = stage + 3; if (istage >= OST) istage -= OST;
            OUT_ISSUE_STAGE(istage, c0 + cc + 3);
            CP_ASYNC_WAIT(3);
        } else {
            const int rem = nc - 1 - cc;          // 2, 1, 0
            if (rem == 2)      CP_ASYNC_WAIT(2);
            else if (rem == 1) CP_ASYNC_WAIT(1);
            else               CP_ASYNC_WAIT(0);
        }
        __syncthreads();   // stage-cc writes visible; bounds warp skew

        const int c = c0 + cc;
        const float* vrow = vs + (size_t)stage * LM * 128 + hwl;
        float s0 = 0.0f, s1 = 0.0f, t0 = 0.0f, t1 = 0.0f;
#pragma unroll
        for (int m = 0; m < LM; m += 2) {
            const float v0 = vrow[(size_t)m * 128];
            const float v1 = vrow[(size_t)(m + 1) * 128];
            s0 += a0[m] * v0;     t0 += a1[m] * v0;
            s1 += a0[m + 1] * v1; t1 += a1[m + 1] * v1;
        }
        op0[(size_t)c * HW] = fmp0[(size_t)c * HW] + 0.5f * (s0 + s1);
        op1[(size_t)c * HW] = fmp1[(size_t)c * HW] + 0.5f * (t0 + t1);

        if (++stage == OST) stage = 0;
    }
#undef OUT_ISSUE_STAGE
}

// ---------------------------------------------------------------------------
// Launch: 2-chunk x 2-stream software pipeline over hw.
// Chunk 0 runs its full chain on the (captured) default stream; chunk 1 runs
// on a side stream, staggered to start after chunk 0's qproj (event eA).
// Overlaps chunk 1's compute-bound qproj (DRAM 4%) with chunk 0's DRAM-bound
// attn/out (FMA ~13%). Join: default stream waits eJ before returning.
// Streams/events lazily created on the FIRST (uncaptured correctness) call,
// so they exist before graph capture; fork/join events become graph edges.
// Device work per call is identical and deterministic.
// Inputs (metadata order): fc, fm, key_buffer, value_buffer, Q, K, V.
// concat(new, buffer)[-32:] keeps exactly the buffers -> K and V matrices are
// dead inputs; only q = fc@Q survives.
// ---------------------------------------------------------------------------
extern "C" void kernel_launch(void* const* d_in, const int* in_sizes, int n_in,
                              void* d_out, int out_size) {
    const float* fc   = (const float*)d_in[0];
    const float* fm   = (const float*)d_in[1];
    const float* keyb = (const float*)d_in[2];
    const float* valb = (const float*)d_in[3];
    const float* Qm   = (const float*)d_in[4];
    float* out = (float*)d_out;

    static cudaStream_t s1 = nullptr;
    static cudaEvent_t  eA = nullptr, eJ = nullptr;
    if (s1 == nullptr) {
        cudaStreamCreateWithFlags(&s1, cudaStreamNonBlocking);
        cudaEventCreateWithFlags(&eA, cudaEventDisableTiming);
        cudaEventCreateWithFlags(&eJ, cudaEventDisableTiming);
    }

    const int red_bytes = DSP * LM * NB * 64 * sizeof(float);  // 64KB
    const int fin_bytes = DQ * NB * LM * 32 * sizeof(float);   // 64KB
    const int out_bytes = OST * LM * 128 * sizeof(float);      // 96KB
    cudaFuncSetAttribute(attn_partial_kernel,
                         cudaFuncAttributeMaxDynamicSharedMemorySize, red_bytes);
    cudaFuncSetAttribute(attn_finish_kernel,
                         cudaFuncAttributeMaxDynamicSharedMemorySize, fin_bytes);
    cudaFuncSetAttribute(out_kernel,
                         cudaFuncAttributeMaxDynamicSharedMemorySize, out_bytes);

    // ---- chunk 0 chain on default stream ----
    qproj_kernel<<<dim3(HWC / 128, DK / 128, NB), 256, 0, 0>>>(fc, Qm, 0);
    cudaEventRecord(eA, 0);   // stagger marker: chunk-0 qproj done
    attn_partial_kernel<<<dim3(HWC / 64, DQ), 256, red_bytes, 0>>>(keyb, 0);
    attn_finish_kernel<<<dim3(HWC / 32), 512, fin_bytes, 0>>>(0);
    out_kernel<<<dim3(HWC / 128, NCH), 256, out_bytes, 0>>>(fm, valb, out, 0);

    // ---- chunk 1 chain on side stream, staggered ----
    cudaStreamWaitEvent(s1, eA, 0);
    qproj_kernel<<<dim3(HWC / 128, DK / 128, NB), 256, 0, s1>>>(fc, Qm, HWC);
    attn_partial_kernel<<<dim3(HWC / 64, DQ), 256, red_bytes, s1>>>(keyb, HWC);
    attn_finish_kernel<<<dim3(HWC / 32), 512, fin_bytes, s1>>>(HWC);
    out_kernel<<<dim3(HWC / 128, NCH), 256, out_bytes, s1>>>(fm, valb, out, HWC);

    // ---- join back to default stream ----
    cudaEventRecord(eJ, s1);
    cudaStreamWaitEvent((cudaStream_t)0, eJ, 0);
}